// round 5
// baseline (speedup 1.0000x reference)
#include <cuda_runtime.h>
#include <cuda_fp16.h>
#include <cstdint>
#include <cstddef>

// Problem constants
#define M_DIM 8192
#define K_DIM 4096
#define N_DIM 11008
#define NPACK (N_DIM / 8)
#define KPACK (K_DIM / 8)

// GEMM tiling: block 128x128x32, 8 warps (2M x 4N), warp tile 64x32
#define BM 128
#define BN 128
#define BK 32
#define NSTAGE 4
#define NT (K_DIM / BK)        // 128
#define A_LD 40                // halves per A row (80B, conflict-free ldmatrix)
#define B_LD 136               // halves per B row (272B, conflict-free trans ldmatrix)
#define A_BYTES (BM * A_LD * 2)   // 10240
#define B_BYTES (BK * B_LD * 2)   // 8704
#define STAGE_BYTES (A_BYTES + B_BYTES)       // 18944
#define SMEM_TOTAL (NSTAGE * STAGE_BYTES)     // 75776 (x2 CTAs = 151552, fits)

#define MT_TILES (M_DIM / BM)  // 64
#define NT_TILES (N_DIM / BN)  // 86

// Device scratch (allocation-free rule)
__device__ __half g_xh[(size_t)M_DIM * K_DIM];   // x in fp16 [M,K]
__device__ __half g_wh[(size_t)K_DIM * N_DIM];   // dequant W fp16 [K,N]

// ---------------------------------------------------------------------------
// Kernel 0: x fp32 -> fp16
// ---------------------------------------------------------------------------
__global__ void convert_x(const float* __restrict__ x) {
    size_t i = ((size_t)blockIdx.x * 256 + threadIdx.x) * 8;
    float4 a = *(const float4*)(x + i);
    float4 b = *(const float4*)(x + i + 4);
    __half2 h0 = __floats2half2_rn(a.x, a.y);
    __half2 h1 = __floats2half2_rn(a.z, a.w);
    __half2 h2 = __floats2half2_rn(b.x, b.y);
    __half2 h3 = __floats2half2_rn(b.z, b.w);
    uint4 u;
    u.x = *(uint32_t*)&h0; u.y = *(uint32_t*)&h1;
    u.z = *(uint32_t*)&h2; u.w = *(uint32_t*)&h3;
    *(uint4*)(g_xh + i) = u;
}

// ---------------------------------------------------------------------------
// Kernel 1: dequant int4 GPTQ -> fp16 [K, N]   (verified R2)
// ---------------------------------------------------------------------------
__global__ void dequant_kernel(const int* __restrict__ qweight,
                               const int* __restrict__ qzeros,
                               const void* __restrict__ scales_raw) {
    int pr = blockIdx.y;
    int n  = blockIdx.x * 256 + threadIdx.x;
    int g  = pr >> 4;

    const float* sf = (const float*)scales_raw;
    float probe = sf[0];
    bool is_f32 = (probe > 5e-4f && probe < 5e-2f);

    uint32_t q  = (uint32_t)qweight[(size_t)pr * N_DIM + n];
    uint32_t zq = (uint32_t)qzeros[(size_t)g * NPACK + (n >> 3)];
    float z = (float)((zq >> (4 * (n & 7))) & 15u);
    float s = is_f32 ? sf[(size_t)g * N_DIM + n]
                     : __half2float(((const __half*)scales_raw)[(size_t)g * N_DIM + n]);

    size_t base = (size_t)(pr * 8) * N_DIM + n;
#pragma unroll
    for (int j = 0; j < 8; j++) {
        float w = (float)((q >> (4 * j)) & 15u);
        g_wh[base + (size_t)j * N_DIM] = __float2half_rn((w - z) * s);
    }
}

// ---------------------------------------------------------------------------
// PTX helpers (baseline PTX only)
// ---------------------------------------------------------------------------
__device__ __forceinline__ void ldmatrix_x4(uint32_t& r0, uint32_t& r1,
                                            uint32_t& r2, uint32_t& r3,
                                            uint32_t addr) {
    asm volatile("ldmatrix.sync.aligned.m8n8.x4.shared.b16 {%0,%1,%2,%3}, [%4];"
                 : "=r"(r0), "=r"(r1), "=r"(r2), "=r"(r3) : "r"(addr));
}
__device__ __forceinline__ void ldmatrix_x4_trans(uint32_t& r0, uint32_t& r1,
                                                  uint32_t& r2, uint32_t& r3,
                                                  uint32_t addr) {
    asm volatile("ldmatrix.sync.aligned.m8n8.x4.trans.shared.b16 {%0,%1,%2,%3}, [%4];"
                 : "=r"(r0), "=r"(r1), "=r"(r2), "=r"(r3) : "r"(addr));
}
__device__ __forceinline__ void mma16816(float* c, const uint32_t* a, const uint32_t* b) {
    asm volatile(
        "mma.sync.aligned.m16n8k16.row.col.f32.f16.f16.f32 "
        "{%0,%1,%2,%3}, {%4,%5,%6,%7}, {%8,%9}, {%0,%1,%2,%3};"
        : "+f"(c[0]), "+f"(c[1]), "+f"(c[2]), "+f"(c[3])
        : "r"(a[0]), "r"(a[1]), "r"(a[2]), "r"(a[3]), "r"(b[0]), "r"(b[1]));
}
__device__ __forceinline__ void cp_async16(uint32_t dst, const void* src) {
    asm volatile("cp.async.cg.shared.global [%0], [%1], 16;"
                 :: "r"(dst), "l"(src) : "memory");
}

// ---------------------------------------------------------------------------
// Kernel 2: HMMA GEMM, cp.async 4-stage pipeline, 2 CTAs/SM
// ---------------------------------------------------------------------------
__global__ __launch_bounds__(256, 2)
void gemm_kernel(float* __restrict__ out) {
    extern __shared__ char smem[];
    const uint32_t sbase = (uint32_t)__cvta_generic_to_shared(smem);

    const int tid  = threadIdx.x;
    const int lane = tid & 31;
    const int wid  = tid >> 5;
    const int warp_m = wid & 1;    // 0..1 (64 rows each)
    const int warp_n = wid >> 1;   // 0..3 (32 cols each)

    const int m0 = blockIdx.y * BM;
    const int n0 = blockIdx.x * BN;

    const __half* asrc = g_xh + (size_t)m0 * K_DIM;
    const __half* bsrc = g_wh + n0;

    // cp.async chunk coords: A 128 rows x 4 chunks (2/thread), B 32 rows x 16 chunks (2/thread)
    const int ar = tid >> 2, ac = tid & 3;
    const int br = tid >> 4, bc = tid & 15;

    auto issue_stage = [&](int kt) {
        const int slot = kt & (NSTAGE - 1);
        const int k0 = kt * BK;
        uint32_t abase = sbase + slot * STAGE_BYTES;
        uint32_t bbase = abase + A_BYTES;
#pragma unroll
        for (int i = 0; i < 2; i++) {
            int r = ar + i * 64;
            cp_async16(abase + r * (A_LD * 2) + ac * 16,
                       asrc + (size_t)r * K_DIM + k0 + ac * 8);
        }
#pragma unroll
        for (int i = 0; i < 2; i++) {
            int r = br + i * 16;
            cp_async16(bbase + r * (B_LD * 2) + bc * 16,
                       bsrc + (size_t)(k0 + r) * N_DIM + bc * 8);
        }
        asm volatile("cp.async.commit_group;" ::: "memory");
    };

    float acc[4][4][4];
#pragma unroll
    for (int i = 0; i < 4; i++)
#pragma unroll
        for (int j = 0; j < 4; j++) {
            acc[i][j][0] = 0.f; acc[i][j][1] = 0.f;
            acc[i][j][2] = 0.f; acc[i][j][3] = 0.f;
        }

    issue_stage(0); issue_stage(1); issue_stage(2);

#pragma unroll 1
    for (int t = 0; t < NT; t++) {
        asm volatile("cp.async.wait_group %0;" :: "n"(NSTAGE - 2) : "memory");
        __syncthreads();

        const int slot = t & (NSTAGE - 1);
        uint32_t abase = sbase + slot * STAGE_BYTES;
        uint32_t bbase = abase + A_BYTES;

#pragma unroll
        for (int ks = 0; ks < 2; ks++) {
            const int kk = ks * 16;
            uint32_t a[4][4];
#pragma unroll
            for (int mi = 0; mi < 4; mi++) {
                int row = warp_m * 64 + mi * 16 + (lane & 15);
                int col = kk + 8 * (lane >> 4);
                ldmatrix_x4(a[mi][0], a[mi][1], a[mi][2], a[mi][3],
                            abase + row * (A_LD * 2) + col * 2);
            }
            uint32_t b[4][2];
#pragma unroll
            for (int nh = 0; nh < 2; nh++) {
                int trow = kk + (lane & 7) + 8 * ((lane >> 3) & 1);
                int tcol = warp_n * 32 + nh * 16 + 8 * (lane >> 4);
                uint32_t r0, r1, r2, r3;
                ldmatrix_x4_trans(r0, r1, r2, r3,
                                  bbase + trow * (B_LD * 2) + tcol * 2);
                b[nh * 2 + 0][0] = r0; b[nh * 2 + 0][1] = r1;
                b[nh * 2 + 1][0] = r2; b[nh * 2 + 1][1] = r3;
            }
#pragma unroll
            for (int mi = 0; mi < 4; mi++)
#pragma unroll
                for (int ni = 0; ni < 4; ni++)
                    mma16816(acc[mi][ni], a[mi], b[ni]);
        }

        __syncthreads();
        if (t + 3 < NT) issue_stage(t + 3);
    }

    // Epilogue: round through fp16, write float2
    const int g4 = lane >> 2, t4 = lane & 3;
#pragma unroll
    for (int mi = 0; mi < 4; mi++) {
#pragma unroll
        for (int ni = 0; ni < 4; ni++) {
            int row = m0 + warp_m * 64 + mi * 16 + g4;
            int col = n0 + warp_n * 32 + ni * 8 + t4 * 2;
            float2 v0, v1;
            v0.x = __half2float(__float2half_rn(acc[mi][ni][0]));
            v0.y = __half2float(__float2half_rn(acc[mi][ni][1]));
            v1.x = __half2float(__float2half_rn(acc[mi][ni][2]));
            v1.y = __half2float(__float2half_rn(acc[mi][ni][3]));
            *(float2*)(out + (size_t)row * N_DIM + col)       = v0;
            *(float2*)(out + (size_t)(row + 8) * N_DIM + col) = v1;
        }
    }
}

// ---------------------------------------------------------------------------
extern "C" void kernel_launch(void* const* d_in, const int* in_sizes, int n_in,
                              void* d_out, int out_size) {
    const float* x       = (const float*)d_in[0];
    const int*   qweight = (const int*)d_in[1];
    const int*   qzeros  = (const int*)d_in[2];
    const void*  scales  = d_in[3];
    float* out = (float*)d_out;

    convert_x<<<16384, 256>>>(x);
    dequant_kernel<<<dim3(43, KPACK), 256>>>(qweight, qzeros, scales);

    cudaFuncSetAttribute(gemm_kernel,
                         cudaFuncAttributeMaxDynamicSharedMemorySize, SMEM_TOTAL);
    gemm_kernel<<<dim3(NT_TILES, MT_TILES), 256, SMEM_TOTAL>>>(out);
}

// round 6
// speedup vs baseline: 1.4814x; 1.4814x over previous
#include <cuda_runtime.h>
#include <cuda_fp16.h>
#include <cstdint>
#include <cstddef>

// Problem constants
#define M_DIM 8192
#define K_DIM 4096
#define N_DIM 11008
#define NPACK (N_DIM / 8)
#define KPACK (K_DIM / 8)

// GEMM tiling: block 128x128x32, 8 warps (2M x 4N), warp tile 64x32
#define BM 128
#define BN 128
#define BK 32
#define NT (K_DIM / BK)        // 128
#define A_LD 40                // halves per A row (80B, conflict-free ldmatrix)
#define B_LD 136               // halves per B row (272B, conflict-free trans ldmatrix)
#define A_BYTES (BM * A_LD * 2)   // 10240
#define B_BYTES (BK * B_LD * 2)   // 8704
#define STAGE_BYTES (A_BYTES + B_BYTES)   // 18944
#define SMEM_TOTAL (2 * STAGE_BYTES)      // 37888 (x2 CTAs = 75776, fits easily)

#define MT_TILES (M_DIM / BM)  // 64
#define NT_TILES (N_DIM / BN)  // 86

// Device scratch (allocation-free rule)
__device__ __half g_xh[(size_t)M_DIM * K_DIM];   // x in fp16 [M,K]
__device__ __half g_wh[(size_t)K_DIM * N_DIM];   // dequant W fp16 [K,N]

// ---------------------------------------------------------------------------
// Kernel 0: x fp32 -> fp16
// ---------------------------------------------------------------------------
__global__ void convert_x(const float* __restrict__ x) {
    size_t i = ((size_t)blockIdx.x * 256 + threadIdx.x) * 8;
    float4 a = *(const float4*)(x + i);
    float4 b = *(const float4*)(x + i + 4);
    __half2 h0 = __floats2half2_rn(a.x, a.y);
    __half2 h1 = __floats2half2_rn(a.z, a.w);
    __half2 h2 = __floats2half2_rn(b.x, b.y);
    __half2 h3 = __floats2half2_rn(b.z, b.w);
    uint4 u;
    u.x = *(uint32_t*)&h0; u.y = *(uint32_t*)&h1;
    u.z = *(uint32_t*)&h2; u.w = *(uint32_t*)&h3;
    *(uint4*)(g_xh + i) = u;
}

// ---------------------------------------------------------------------------
// Kernel 1: dequant int4 GPTQ -> fp16 [K, N]   (verified R2)
// ---------------------------------------------------------------------------
__global__ void dequant_kernel(const int* __restrict__ qweight,
                               const int* __restrict__ qzeros,
                               const void* __restrict__ scales_raw) {
    int pr = blockIdx.y;
    int n  = blockIdx.x * 256 + threadIdx.x;
    int g  = pr >> 4;

    const float* sf = (const float*)scales_raw;
    float probe = sf[0];
    bool is_f32 = (probe > 5e-4f && probe < 5e-2f);

    uint32_t q  = (uint32_t)qweight[(size_t)pr * N_DIM + n];
    uint32_t zq = (uint32_t)qzeros[(size_t)g * NPACK + (n >> 3)];
    float z = (float)((zq >> (4 * (n & 7))) & 15u);
    float s = is_f32 ? sf[(size_t)g * N_DIM + n]
                     : __half2float(((const __half*)scales_raw)[(size_t)g * N_DIM + n]);

    size_t base = (size_t)(pr * 8) * N_DIM + n;
#pragma unroll
    for (int j = 0; j < 8; j++) {
        float w = (float)((q >> (4 * j)) & 15u);
        g_wh[base + (size_t)j * N_DIM] = __float2half_rn((w - z) * s);
    }
}

// ---------------------------------------------------------------------------
// PTX helpers (baseline PTX only)
// ---------------------------------------------------------------------------
__device__ __forceinline__ void ldmatrix_x4(uint32_t& r0, uint32_t& r1,
                                            uint32_t& r2, uint32_t& r3,
                                            uint32_t addr) {
    asm volatile("ldmatrix.sync.aligned.m8n8.x4.shared.b16 {%0,%1,%2,%3}, [%4];"
                 : "=r"(r0), "=r"(r1), "=r"(r2), "=r"(r3) : "r"(addr));
}
__device__ __forceinline__ void ldmatrix_x4_trans(uint32_t& r0, uint32_t& r1,
                                                  uint32_t& r2, uint32_t& r3,
                                                  uint32_t addr) {
    asm volatile("ldmatrix.sync.aligned.m8n8.x4.trans.shared.b16 {%0,%1,%2,%3}, [%4];"
                 : "=r"(r0), "=r"(r1), "=r"(r2), "=r"(r3) : "r"(addr));
}
__device__ __forceinline__ void mma16816(float* c, const uint32_t* a, const uint32_t* b) {
    asm volatile(
        "mma.sync.aligned.m16n8k16.row.col.f32.f16.f16.f32 "
        "{%0,%1,%2,%3}, {%4,%5,%6,%7}, {%8,%9}, {%0,%1,%2,%3};"
        : "+f"(c[0]), "+f"(c[1]), "+f"(c[2]), "+f"(c[3])
        : "r"(a[0]), "r"(a[1]), "r"(a[2]), "r"(a[3]), "r"(b[0]), "r"(b[1]));
}

// ---------------------------------------------------------------------------
// Kernel 2: HMMA GEMM, LDG+STS double-buffered, ONE barrier per k-tile
// ---------------------------------------------------------------------------
__global__ __launch_bounds__(256, 2)
void gemm_kernel(float* __restrict__ out) {
    __shared__ char smem[SMEM_TOTAL];
    const uint32_t sbase = (uint32_t)__cvta_generic_to_shared(smem);

    const int tid  = threadIdx.x;
    const int lane = tid & 31;
    const int wid  = tid >> 5;
    const int warp_m = wid & 1;    // 0..1 (64 rows each)
    const int warp_n = wid >> 1;   // 0..3 (32 cols each)

    const int m0 = blockIdx.y * BM;
    const int n0 = blockIdx.x * BN;

    const __half* asrc = g_xh + (size_t)m0 * K_DIM;
    const __half* bsrc = g_wh + n0;

    // Load coords: A 128 rows x 4 chunks (2/thread), B 32 rows x 16 chunks (2/thread)
    const int ar = tid >> 2, ac = tid & 3;
    const int br = tid >> 4, bc = tid & 15;

    uint4 areg[2], breg[2];

    auto load_tile = [&](int kt) {
        const int k0 = kt * BK;
#pragma unroll
        for (int i = 0; i < 2; i++)
            areg[i] = *(const uint4*)(asrc + (size_t)(ar + i * 64) * K_DIM + k0 + ac * 8);
#pragma unroll
        for (int i = 0; i < 2; i++)
            breg[i] = *(const uint4*)(bsrc + (size_t)(k0 + br + i * 16) * N_DIM + bc * 8);
    };
    auto store_tile = [&](int buf) {
        uint32_t abase = sbase + buf * STAGE_BYTES;
        uint32_t bbase = abase + A_BYTES;
#pragma unroll
        for (int i = 0; i < 2; i++)
            *(uint4*)(smem + (abase - sbase) + (ar + i * 64) * (A_LD * 2) + ac * 16) = areg[i];
#pragma unroll
        for (int i = 0; i < 2; i++)
            *(uint4*)(smem + (bbase - sbase) + (br + i * 16) * (B_LD * 2) + bc * 16) = breg[i];
    };

    float acc[4][4][4];
#pragma unroll
    for (int i = 0; i < 4; i++)
#pragma unroll
        for (int j = 0; j < 4; j++) {
            acc[i][j][0] = 0.f; acc[i][j][1] = 0.f;
            acc[i][j][2] = 0.f; acc[i][j][3] = 0.f;
        }

    auto compute = [&](int buf) {
        uint32_t abase = sbase + buf * STAGE_BYTES;
        uint32_t bbase = abase + A_BYTES;
#pragma unroll
        for (int ks = 0; ks < 2; ks++) {
            const int kk = ks * 16;
            uint32_t a[4][4];
#pragma unroll
            for (int mi = 0; mi < 4; mi++) {
                int row = warp_m * 64 + mi * 16 + (lane & 15);
                int col = kk + 8 * (lane >> 4);
                ldmatrix_x4(a[mi][0], a[mi][1], a[mi][2], a[mi][3],
                            abase + row * (A_LD * 2) + col * 2);
            }
            uint32_t b[4][2];
#pragma unroll
            for (int nh = 0; nh < 2; nh++) {
                int trow = kk + (lane & 7) + 8 * ((lane >> 3) & 1);
                int tcol = warp_n * 32 + nh * 16 + 8 * (lane >> 4);
                uint32_t r0, r1, r2, r3;
                ldmatrix_x4_trans(r0, r1, r2, r3,
                                  bbase + trow * (B_LD * 2) + tcol * 2);
                b[nh * 2 + 0][0] = r0; b[nh * 2 + 0][1] = r1;
                b[nh * 2 + 1][0] = r2; b[nh * 2 + 1][1] = r3;
            }
#pragma unroll
            for (int mi = 0; mi < 4; mi++)
#pragma unroll
                for (int ni = 0; ni < 4; ni++)
                    mma16816(acc[mi][ni], a[mi], b[ni]);
        }
    };

    // Prologue: buf0 <- tile0; regs <- tile1
    load_tile(0);
    store_tile(0);
    load_tile(1);
    __syncthreads();

    // Steady state: ONE barrier per k-tile.
    // Iter t: regs hold tile t+1 -> STS to buf nxt; LDG tile t+2 -> regs;
    //         compute buf cur; barrier.
#pragma unroll 1
    for (int t = 0; t < NT; t++) {
        const int cur = t & 1, nxt = cur ^ 1;
        if (t + 1 < NT) store_tile(nxt);
        if (t + 2 < NT) load_tile(t + 2);
        compute(cur);
        __syncthreads();
    }

    // Epilogue: round through fp16, write float2
    const int g4 = lane >> 2, t4 = lane & 3;
#pragma unroll
    for (int mi = 0; mi < 4; mi++) {
#pragma unroll
        for (int ni = 0; ni < 4; ni++) {
            int row = m0 + warp_m * 64 + mi * 16 + g4;
            int col = n0 + warp_n * 32 + ni * 8 + t4 * 2;
            float2 v0, v1;
            v0.x = __half2float(__float2half_rn(acc[mi][ni][0]));
            v0.y = __half2float(__float2half_rn(acc[mi][ni][1]));
            v1.x = __half2float(__float2half_rn(acc[mi][ni][2]));
            v1.y = __half2float(__float2half_rn(acc[mi][ni][3]));
            *(float2*)(out + (size_t)row * N_DIM + col)       = v0;
            *(float2*)(out + (size_t)(row + 8) * N_DIM + col) = v1;
        }
    }
}

// ---------------------------------------------------------------------------
extern "C" void kernel_launch(void* const* d_in, const int* in_sizes, int n_in,
                              void* d_out, int out_size) {
    const float* x       = (const float*)d_in[0];
    const int*   qweight = (const int*)d_in[1];
    const int*   qzeros  = (const int*)d_in[2];
    const void*  scales  = d_in[3];
    float* out = (float*)d_out;

    convert_x<<<16384, 256>>>(x);
    dequant_kernel<<<dim3(43, KPACK), 256>>>(qweight, qzeros, scales);

    gemm_kernel<<<dim3(NT_TILES, MT_TILES), 256>>>(out);
}